// round 1
// baseline (speedup 1.0000x reference)
#include <cuda_runtime.h>

#define NDST 100000
#define NE   1000000
#define UN   200000
#define UE   100000
#define UT   100000
#define DN_  172
#define DT_  100
#define DO_  100
#define NEG_SLOPE 0.2f

// ---------------- scratch (device globals; no allocation) ----------------
__device__ float    g_TF  [UT * DT_];        // time features       40 MB
__device__ float    g_Q   [NDST * DO_];      // per-dst query       40 MB
__device__ float    g_KVN [UN * 2 * DO_];    // node kv table      160 MB
__device__ float    g_KVE [UE * 2 * DO_];    // edge kv table       80 MB
__device__ float    g_KVT [UT * 2 * DO_];    // time kv table       80 MB
__device__ float    g_attn[NE * 2];          // per-edge attn        8 MB
__device__ unsigned g_m   [NDST * 2];        // encoded seg max
__device__ float    g_s   [NDST * 2];        // seg sum of exp
__device__ float    g_acc [NDST * DO_];      // weighted V accum    40 MB
__device__ float    g_biasq[DO_];            // bqn + bqt + cos(tb)@Wqt

// order-preserving float<->uint encoding for atomicMax
__device__ __forceinline__ unsigned f2u_ord(float f) {
    unsigned u = __float_as_uint(f);
    return (u & 0x80000000u) ? ~u : (u | 0x80000000u);
}
__device__ __forceinline__ float u2f_ord(unsigned u) {
    return (u & 0x80000000u) ? __uint_as_float(u & 0x7fffffffu)
                             : __uint_as_float(~u);
}

// ---------------- init ----------------
__global__ void init_kernel() {
    int idx = blockIdx.x * blockDim.x + threadIdx.x;
    int stride = gridDim.x * blockDim.x;
    for (int i = idx; i < NDST * DO_; i += stride) g_acc[i] = 0.f;
    for (int i = idx; i < 2 * NDST; i += stride) { g_s[i] = 0.f; g_m[i] = 0u; }
}

// ---------------- q bias: bqn + bqt + cos(time_b) @ Wqt ----------------
__global__ void biasq_kernel(const float* __restrict__ time_b,
                             const float* __restrict__ Wqt,
                             const float* __restrict__ bqt,
                             const float* __restrict__ bqn) {
    int j = threadIdx.x;
    if (j >= DO_) return;
    float acc = bqt[j] + bqn[j];
    for (int k = 0; k < DT_; k++) acc += cosf(time_b[k]) * Wqt[k * DO_ + j];
    g_biasq[j] = acc;
}

// ---------------- time features ----------------
__global__ void timefeat_kernel(const float* __restrict__ utd,
                                const float* __restrict__ tw,
                                const float* __restrict__ tb) {
    int idx = blockIdx.x * blockDim.x + threadIdx.x;
    int stride = gridDim.x * blockDim.x;
    for (int i = idx; i < UT * DT_; i += stride) {
        int t = i / DT_, j = i - t * DT_;
        g_TF[i] = cosf(utd[t] * tw[j] + tb[j]);
    }
}

// ---------------- generic tiled fp32 GEMM: C = (gather?)A @ W + bias ----------------
template <bool GATHER>
__global__ __launch_bounds__(256)
void gemm_bias_kernel(const float* __restrict__ A, const float* __restrict__ W,
                      const float* __restrict__ bias, float* __restrict__ C,
                      const int* __restrict__ gidx, int M, int K, int N) {
    const int BM = 64, BN = 64, BK = 16;
    __shared__ __align__(16) float As[BK][BM];
    __shared__ __align__(16) float Ws[BK][BN];
    int tid = threadIdx.x;
    int tx = tid & 15, ty = tid >> 4;
    int m0 = blockIdx.y * BM;
    int n0 = blockIdx.x * BN;

    float acc[4][4] = {};

    int ra = tid >> 2;            // 0..63  (A row within tile)
    int ka = (tid & 3) * 4;       // 0,4,8,12 (A k offset)
    int arow = m0 + ra;
    long abase = -1;
    if (arow < M) {
        int src = GATHER ? gidx[arow] : arow;
        abase = (long)src * K;
    }
    int kw = tid >> 4;            // 0..15 (W k row)
    int cw = (tid & 15) * 4;      // 0..60 (W col offset)

    for (int k0 = 0; k0 < K; k0 += BK) {
        float4 av = make_float4(0.f, 0.f, 0.f, 0.f);
        if (abase >= 0) {
            int kk = k0 + ka;
            if (kk + 3 < K) {
                av = *(const float4*)(A + abase + kk);
            } else {
                if (kk + 0 < K) av.x = A[abase + kk + 0];
                if (kk + 1 < K) av.y = A[abase + kk + 1];
                if (kk + 2 < K) av.z = A[abase + kk + 2];
                if (kk + 3 < K) av.w = A[abase + kk + 3];
            }
        }
        As[ka + 0][ra] = av.x;
        As[ka + 1][ra] = av.y;
        As[ka + 2][ra] = av.z;
        As[ka + 3][ra] = av.w;

        float4 wv = make_float4(0.f, 0.f, 0.f, 0.f);
        {
            int kk = k0 + kw;
            int cc = n0 + cw;
            if (kk < K && cc < N) wv = *(const float4*)(W + (long)kk * N + cc);
        }
        *(float4*)&Ws[kw][cw] = wv;
        __syncthreads();

#pragma unroll
        for (int kk = 0; kk < BK; kk++) {
            float4 a4 = *(const float4*)&As[kk][ty * 4];
            float4 b4 = *(const float4*)&Ws[kk][tx * 4];
            float aa[4] = {a4.x, a4.y, a4.z, a4.w};
            float bb[4] = {b4.x, b4.y, b4.z, b4.w};
#pragma unroll
            for (int i = 0; i < 4; i++)
#pragma unroll
                for (int j = 0; j < 4; j++) acc[i][j] += aa[i] * bb[j];
        }
        __syncthreads();
    }

    int c = n0 + tx * 4;
    if (c < N) {  // N is a multiple of 4, so the whole float4 is valid
        float4 b4 = *(const float4*)(bias + c);
#pragma unroll
        for (int i = 0; i < 4; i++) {
            int r = m0 + ty * 4 + i;
            if (r >= M) continue;
            float4 o = make_float4(acc[i][0] + b4.x, acc[i][1] + b4.y,
                                   acc[i][2] + b4.z, acc[i][3] + b4.w);
            *(float4*)(C + (long)r * N + c) = o;
        }
    }
}

// ---------------- edge pass 1: attn + segment max ----------------
__global__ __launch_bounds__(256)
void edge_pass1(const int* __restrict__ node_inv, const int* __restrict__ eids,
                const int* __restrict__ tids, const int* __restrict__ dsti) {
    int e = (int)((blockIdx.x * (long)blockDim.x + threadIdx.x) >> 5);
    int lane = threadIdx.x & 31;
    if (e >= NE) return;
    int dst = dsti[e];
    float s0 = 0.f, s1 = 0.f;
    if (lane < 25) {
        const float4* qr = (const float4*)(g_Q + (long)dst * DO_);
        const float4* kn = (const float4*)(g_KVN + (long)node_inv[e] * (2 * DO_));
        const float4* ke = (const float4*)(g_KVE + (long)eids[e] * (2 * DO_));
        const float4* kt = (const float4*)(g_KVT + (long)tids[e] * (2 * DO_));
        float4 a = qr[lane];
        float4 b = kn[lane];
        float4 c = ke[lane];
        float4 d = kt[lane];
        float p0 = a.x * (b.x + c.x + d.x);
        float p1 = a.y * (b.y + c.y + d.y);
        float p2 = a.z * (b.z + c.z + d.z);
        float p3 = a.w * (b.w + c.w + d.w);
        int base = lane * 4;
        if (base + 0 < 50) s0 += p0; else s1 += p0;
        if (base + 1 < 50) s0 += p1; else s1 += p1;
        if (base + 2 < 50) s0 += p2; else s1 += p2;
        if (base + 3 < 50) s0 += p3; else s1 += p3;
    }
#pragma unroll
    for (int off = 16; off; off >>= 1) {
        s0 += __shfl_down_sync(0xffffffffu, s0, off);
        s1 += __shfl_down_sync(0xffffffffu, s1, off);
    }
    if (lane == 0) {
        float a0 = s0 > 0.f ? s0 : NEG_SLOPE * s0;
        float a1 = s1 > 0.f ? s1 : NEG_SLOPE * s1;
        g_attn[2 * e + 0] = a0;
        g_attn[2 * e + 1] = a1;
        atomicMax(g_m + 2 * dst + 0, f2u_ord(a0));
        atomicMax(g_m + 2 * dst + 1, f2u_ord(a1));
    }
}

// ---------------- edge pass 2: exp, segment sums, weighted V scatter ----------------
__global__ __launch_bounds__(256)
void edge_pass2(const int* __restrict__ node_inv, const int* __restrict__ eids,
                const int* __restrict__ tids, const int* __restrict__ dsti) {
    int e = (int)((blockIdx.x * (long)blockDim.x + threadIdx.x) >> 5);
    int lane = threadIdx.x & 31;
    if (e >= NE) return;
    int dst = dsti[e];
    float m0 = u2f_ord(g_m[2 * dst + 0]);
    float m1 = u2f_ord(g_m[2 * dst + 1]);
    float w0 = __expf(g_attn[2 * e + 0] - m0);
    float w1 = __expf(g_attn[2 * e + 1] - m1);
    if (lane == 0) atomicAdd(g_s + 2 * dst + 0, w0);
    if (lane == 1) atomicAdd(g_s + 2 * dst + 1, w1);
    if (lane < 25) {
        const float4* kn = (const float4*)(g_KVN + (long)node_inv[e] * (2 * DO_));
        const float4* ke = (const float4*)(g_KVE + (long)eids[e] * (2 * DO_));
        const float4* kt = (const float4*)(g_KVT + (long)tids[e] * (2 * DO_));
        float4 b = kn[25 + lane];
        float4 c = ke[25 + lane];
        float4 d = kt[25 + lane];
        int base = lane * 4;
        float vx = (b.x + c.x + d.x) * (base + 0 < 50 ? w0 : w1);
        float vy = (b.y + c.y + d.y) * (base + 1 < 50 ? w0 : w1);
        float vz = (b.z + c.z + d.z) * (base + 2 < 50 ? w0 : w1);
        float vw = (b.w + c.w + d.w) * (base + 3 < 50 ? w0 : w1);
        float* p = g_acc + (long)dst * DO_ + base;
        atomicAdd(p + 0, vx);
        atomicAdd(p + 1, vy);
        atomicAdd(p + 2, vz);
        atomicAdd(p + 3, vw);
    }
}

// ---------------- finalize: out-proj + relu + layernorm ----------------
// dynamic smem: Wt[100][273] (transposed Wout, padded) + xs[4][272] + outs[4][100]
#define FIN_SMEM_FLOATS (DO_ * 273 + 4 * 272 + 4 * DO_)
__global__ __launch_bounds__(128)
void finalize_kernel(const float* __restrict__ nodeData,
                     const int* __restrict__ rev_nids,
                     const float* __restrict__ Wout,
                     const float* __restrict__ bout,
                     const float* __restrict__ ln_g,
                     const float* __restrict__ ln_b,
                     float* __restrict__ out) {
    extern __shared__ float sm[];
    float* Wt   = sm;                   // 100*273
    float* xs   = Wt + DO_ * 273;       // 4*272
    float* outs = xs + 4 * 272;         // 4*100
    int tid = threadIdx.x;

    for (int i = tid; i < 272 * DO_; i += blockDim.x) {
        int k = i / DO_, j = i - k * DO_;
        Wt[j * 273 + k] = Wout[i];
    }
    __syncthreads();

    for (int r0 = blockIdx.x * 4; r0 < NDST; r0 += gridDim.x * 4) {
        for (int i = tid; i < 4 * 272; i += blockDim.x) {
            int r = i / 272, k = i - r * 272;
            int row = r0 + r;
            float v = 0.f;
            if (row < NDST) {
                if (k < DO_) {
                    float sv = g_s[2 * row + (k < 50 ? 0 : 1)];
                    v = sv > 0.f ? g_acc[(long)row * DO_ + k] / sv : 0.f;
                } else {
                    v = nodeData[(long)rev_nids[row] * DN_ + (k - DO_)];
                }
            }
            xs[r * 272 + k] = v;
        }
        __syncthreads();

        if (tid < DO_) {
            const float* wrow = Wt + tid * 273;
            float a0 = 0.f, a1 = 0.f, a2 = 0.f, a3 = 0.f;
#pragma unroll 4
            for (int k = 0; k < 272; k += 4) {
                float w0 = wrow[k], w1 = wrow[k + 1], w2 = wrow[k + 2], w3 = wrow[k + 3];
                float4 x0 = *(const float4*)(xs + 0 * 272 + k);
                float4 x1 = *(const float4*)(xs + 1 * 272 + k);
                float4 x2 = *(const float4*)(xs + 2 * 272 + k);
                float4 x3 = *(const float4*)(xs + 3 * 272 + k);
                a0 += w0 * x0.x + w1 * x0.y + w2 * x0.z + w3 * x0.w;
                a1 += w0 * x1.x + w1 * x1.y + w2 * x1.z + w3 * x1.w;
                a2 += w0 * x2.x + w1 * x2.y + w2 * x2.z + w3 * x2.w;
                a3 += w0 * x3.x + w1 * x3.y + w2 * x3.z + w3 * x3.w;
            }
            float bj = bout[tid];
            float v0 = a0 + bj, v1 = a1 + bj, v2 = a2 + bj, v3 = a3 + bj;
            outs[0 * DO_ + tid] = v0 > 0.f ? v0 : 0.f;
            outs[1 * DO_ + tid] = v1 > 0.f ? v1 : 0.f;
            outs[2 * DO_ + tid] = v2 > 0.f ? v2 : 0.f;
            outs[3 * DO_ + tid] = v3 > 0.f ? v3 : 0.f;
        }
        __syncthreads();

        int wr = tid >> 5, lane = tid & 31;
        int row = r0 + wr;
        if (row < NDST) {
            float s = 0.f, sq = 0.f;
            for (int j = lane; j < DO_; j += 32) {
                float v = outs[wr * DO_ + j];
                s += v; sq += v * v;
            }
#pragma unroll
            for (int off = 16; off; off >>= 1) {
                s  += __shfl_xor_sync(0xffffffffu, s, off);
                sq += __shfl_xor_sync(0xffffffffu, sq, off);
            }
            float mu  = s / (float)DO_;
            float var = sq / (float)DO_ - mu * mu;
            float inv = rsqrtf(var + 1e-5f);
            for (int j = lane; j < DO_; j += 32) {
                float v = (outs[wr * DO_ + j] - mu) * inv * ln_g[j] + ln_b[j];
                out[(long)row * DO_ + j] = v;
            }
        }
        __syncthreads();
    }
}

// ---------------- launch ----------------
extern "C" void kernel_launch(void* const* d_in, const int* in_sizes, int n_in,
                              void* d_out, int out_size) {
    const float* nodeData = (const float*)d_in[0];
    const float* efeat    = (const float*)d_in[1];
    const float* utd      = (const float*)d_in[2];
    const int*   rev_nids = (const int*)d_in[3];
    const int*   rev_eids = (const int*)d_in[4];
    const int*   rev_tids = (const int*)d_in[5];
    const int*   dstindex = (const int*)d_in[6];
    // d_in[7] = num_dst scalar (compile-time constant NDST)
    const float* time_w   = (const float*)d_in[8];
    const float* time_b   = (const float*)d_in[9];
    const float* Wqn      = (const float*)d_in[10];
    const float* bqn      = (const float*)d_in[11];
    const float* Wqt      = (const float*)d_in[12];
    const float* bqt      = (const float*)d_in[13];
    const float* Wkvn     = (const float*)d_in[14];
    const float* bkvn     = (const float*)d_in[15];
    const float* Wkve     = (const float*)d_in[16];
    const float* bkve     = (const float*)d_in[17];
    const float* Wkvt     = (const float*)d_in[18];
    const float* bkvt     = (const float*)d_in[19];
    const float* Wout     = (const float*)d_in[20];
    const float* bout     = (const float*)d_in[21];
    const float* ln_g     = (const float*)d_in[22];
    const float* ln_b     = (const float*)d_in[23];
    float* out = (float*)d_out;

    float *pTF, *pQ, *pKVN, *pKVE, *pKVT, *pbiasq;
    cudaGetSymbolAddress((void**)&pTF,    g_TF);
    cudaGetSymbolAddress((void**)&pQ,     g_Q);
    cudaGetSymbolAddress((void**)&pKVN,   g_KVN);
    cudaGetSymbolAddress((void**)&pKVE,   g_KVE);
    cudaGetSymbolAddress((void**)&pKVT,   g_KVT);
    cudaGetSymbolAddress((void**)&pbiasq, g_biasq);

    const int* node_inv = rev_nids + NDST;  // reverse_nids[num_dst:]

    init_kernel<<<8192, 256>>>();
    biasq_kernel<<<1, 128>>>(time_b, Wqt, bqt, bqn);
    timefeat_kernel<<<8192, 256>>>(utd, time_w, time_b);

    // q[NDST,100] = nodeData[rev_nids[:NDST]] @ Wqn + (bqn + bqt + cos(tb)@Wqt)
    gemm_bias_kernel<true><<<dim3(2, (NDST + 63) / 64), 256>>>(
        nodeData, Wqn, pbiasq, pQ, rev_nids, NDST, DN_, DO_);
    // kvn[UN,200]
    gemm_bias_kernel<false><<<dim3(4, (UN + 63) / 64), 256>>>(
        nodeData, Wkvn, bkvn, pKVN, nullptr, UN, DN_, 2 * DO_);
    // kve[UE,200]
    gemm_bias_kernel<false><<<dim3(4, (UE + 63) / 64), 256>>>(
        efeat, Wkve, bkve, pKVE, nullptr, UE, DN_, 2 * DO_);
    // kvt[UT,200]
    gemm_bias_kernel<false><<<dim3(4, (UT + 63) / 64), 256>>>(
        pTF, Wkvt, bkvt, pKVT, nullptr, UT, DT_, 2 * DO_);

    // edge passes: 1 warp per edge, 8 edges per 256-thread block
    edge_pass1<<<NE / 8, 256>>>(node_inv, rev_eids, rev_tids, dstindex);
    edge_pass2<<<NE / 8, 256>>>(node_inv, rev_eids, rev_tids, dstindex);

    // finalize
    cudaFuncSetAttribute(finalize_kernel,
                         cudaFuncAttributeMaxDynamicSharedMemorySize,
                         FIN_SMEM_FLOATS * (int)sizeof(float));
    finalize_kernel<<<296, 128, FIN_SMEM_FLOATS * (int)sizeof(float)>>>(
        nodeData, rev_nids, Wout, bout, ln_g, ln_b, out);
}

// round 2
// speedup vs baseline: 1.0150x; 1.0150x over previous
#include <cuda_runtime.h>

#define NDST 100000
#define NE   1000000
#define UN   200000
#define UE   100000
#define UT   100000
#define DN_  172
#define DT_  100
#define DO_  100
#define NEG_SLOPE 0.2f

// ---------------- scratch (device globals; no allocation) ----------------
__device__ float    g_TF  [UT * DT_];        // time features       40 MB
__device__ float    g_Q   [NDST * DO_];      // per-dst query       40 MB
__device__ float    g_KVN [UN * 2 * DO_];    // node kv table      160 MB
__device__ float    g_KVE [UE * 2 * DO_];    // edge kv table       80 MB
__device__ float    g_KVT [UT * 2 * DO_];    // time kv table       80 MB
__device__ float    g_acc [NDST * DO_];      // attention output    40 MB
__device__ float    g_biasq[DO_];            // bqn + bqt + cos(tb)@Wqt
// CSR for edges grouped by dst
__device__ int      g_cnt [NDST];
__device__ int      g_off [NDST + 1];
__device__ int      g_cur [NDST];
__device__ int      g_eidx[NE];

// ---------------- init ----------------
__global__ void init_kernel() {
    int idx = blockIdx.x * blockDim.x + threadIdx.x;
    int stride = gridDim.x * blockDim.x;
    for (int i = idx; i < NDST; i += stride) g_cnt[i] = 0;
}

// ---------------- q bias: bqn + bqt + cos(time_b) @ Wqt ----------------
__global__ void biasq_kernel(const float* __restrict__ time_b,
                             const float* __restrict__ Wqt,
                             const float* __restrict__ bqt,
                             const float* __restrict__ bqn) {
    int j = threadIdx.x;
    if (j >= DO_) return;
    float acc = bqt[j] + bqn[j];
    for (int k = 0; k < DT_; k++) acc += cosf(time_b[k]) * Wqt[k * DO_ + j];
    g_biasq[j] = acc;
}

// ---------------- time features ----------------
__global__ void timefeat_kernel(const float* __restrict__ utd,
                                const float* __restrict__ tw,
                                const float* __restrict__ tb) {
    int idx = blockIdx.x * blockDim.x + threadIdx.x;
    int stride = gridDim.x * blockDim.x;
    for (int i = idx; i < UT * DT_; i += stride) {
        int t = i / DT_, j = i - t * DT_;
        g_TF[i] = cosf(utd[t] * tw[j] + tb[j]);
    }
}

// ---------------- CSR build ----------------
__global__ void hist_kernel(const int* __restrict__ dsti) {
    int idx = blockIdx.x * blockDim.x + threadIdx.x;
    int stride = gridDim.x * blockDim.x;
    for (int e = idx; e < NE; e += stride) atomicAdd(&g_cnt[dsti[e]], 1);
}

#define SCH ((NDST + 1023) / 1024)
__global__ __launch_bounds__(1024)
void scan_kernel() {
    __shared__ int ss[1024];
    int t = threadIdx.x;
    int base = t * SCH;
    int end = base + SCH < NDST ? base + SCH : NDST;
    int sum = 0;
    for (int i = base; i < end; i++) sum += g_cnt[i];
    ss[t] = sum;
    __syncthreads();
    for (int off = 1; off < 1024; off <<= 1) {
        int v = (t >= off) ? ss[t - off] : 0;
        __syncthreads();
        ss[t] += v;
        __syncthreads();
    }
    int run = (t == 0) ? 0 : ss[t - 1];
    for (int i = base; i < end; i++) {
        g_off[i] = run;
        g_cur[i] = run;
        run += g_cnt[i];
    }
    if (t == 1023) g_off[NDST] = NE;
}

__global__ void scatter_kernel(const int* __restrict__ dsti) {
    int idx = blockIdx.x * blockDim.x + threadIdx.x;
    int stride = gridDim.x * blockDim.x;
    for (int e = idx; e < NE; e += stride) {
        int pos = atomicAdd(&g_cur[dsti[e]], 1);
        g_eidx[pos] = e;
    }
}

// ---------------- tiled fp32 GEMM: C = (gather?)A @ W + bias ----------------
// 128x64 tile, BK=16, 256 threads, 8x4 micro-tile
template <bool GATHER>
__global__ __launch_bounds__(256)
void gemm128(const float* __restrict__ A, const float* __restrict__ W,
             const float* __restrict__ bias, float* __restrict__ C,
             const int* __restrict__ gidx, int M, int K, int N) {
    __shared__ __align__(16) float As[16][128];
    __shared__ __align__(16) float Ws[16][64];
    int tid = threadIdx.x;
    int m0 = blockIdx.y * 128, n0 = blockIdx.x * 64;
    int tx = tid & 15, ty = tid >> 4;   // micro: rows ty*8.., cols tx*4..
    float acc[8][4] = {};

    int ar = tid >> 1;                  // 0..127
    int ak = (tid & 1) * 8;             // 0 or 8
    long abase = -1;
    int arow = m0 + ar;
    if (arow < M) abase = (long)(GATHER ? gidx[arow] : arow) * K;

    int wk = tid >> 4;                  // 0..15
    int wc = (tid & 15) * 4;            // 0..60

    for (int k0 = 0; k0 < K; k0 += 16) {
#pragma unroll
        for (int h = 0; h < 2; h++) {
            int kk = k0 + ak + h * 4;
            float4 av = make_float4(0.f, 0.f, 0.f, 0.f);
            if (abase >= 0) {
                if (kk + 3 < K) {
                    av = *(const float4*)(A + abase + kk);
                } else {
                    if (kk + 0 < K) av.x = A[abase + kk + 0];
                    if (kk + 1 < K) av.y = A[abase + kk + 1];
                    if (kk + 2 < K) av.z = A[abase + kk + 2];
                    if (kk + 3 < K) av.w = A[abase + kk + 3];
                }
            }
            As[ak + h * 4 + 0][ar] = av.x;
            As[ak + h * 4 + 1][ar] = av.y;
            As[ak + h * 4 + 2][ar] = av.z;
            As[ak + h * 4 + 3][ar] = av.w;
        }
        {
            int kk = k0 + wk;
            int cc = n0 + wc;
            float4 wv = make_float4(0.f, 0.f, 0.f, 0.f);
            if (kk < K && cc < N) wv = *(const float4*)(W + (long)kk * N + cc);
            *(float4*)&Ws[wk][wc] = wv;
        }
        __syncthreads();
#pragma unroll
        for (int kk = 0; kk < 16; kk++) {
            float4 a0 = *(const float4*)&As[kk][ty * 8];
            float4 a1 = *(const float4*)&As[kk][ty * 8 + 4];
            float4 b  = *(const float4*)&Ws[kk][tx * 4];
            float ar8[8] = {a0.x, a0.y, a0.z, a0.w, a1.x, a1.y, a1.z, a1.w};
            float bc[4]  = {b.x, b.y, b.z, b.w};
#pragma unroll
            for (int i = 0; i < 8; i++)
#pragma unroll
                for (int j = 0; j < 4; j++) acc[i][j] += ar8[i] * bc[j];
        }
        __syncthreads();
    }

    int c = n0 + tx * 4;
    if (c < N) {  // N multiple of 4 -> whole float4 valid
        float4 b4 = *(const float4*)(bias + c);
#pragma unroll
        for (int i = 0; i < 8; i++) {
            int r = m0 + ty * 8 + i;
            if (r >= M) continue;
            float4 o = make_float4(acc[i][0] + b4.x, acc[i][1] + b4.y,
                                   acc[i][2] + b4.z, acc[i][3] + b4.w);
            *(float4*)(C + (long)r * N + c) = o;
        }
    }
}

// ---------------- attention: one warp per dst, online softmax ----------------
__global__ __launch_bounds__(256)
void attn_kernel(const int* __restrict__ node_inv, const int* __restrict__ eids,
                 const int* __restrict__ tids) {
    int w = (int)((blockIdx.x * (long)blockDim.x + threadIdx.x) >> 5);
    int lane = threadIdx.x & 31;
    if (w >= NDST) return;
    int beg = g_off[w], end = g_off[w + 1];

    bool act = lane < 25;
    int base = lane * 4;
    bool h0 = base + 0 < 50, h1 = base + 1 < 50, h2 = base + 2 < 50, h3 = base + 3 < 50;

    float4 q = make_float4(0.f, 0.f, 0.f, 0.f);
    if (act) q = ((const float4*)(g_Q + (long)w * DO_))[lane];

    float4 acc = make_float4(0.f, 0.f, 0.f, 0.f);
    float m0 = -1e30f, m1 = -1e30f, s0 = 0.f, s1 = 0.f;

    for (int j = beg; j < end; j++) {
        int e = g_eidx[j];
        int ni = node_inv[e];
        int ei = eids[e];
        int ti = tids[e];
        const float4* kn = (const float4*)(g_KVN + (long)ni * (2 * DO_));
        const float4* ke = (const float4*)(g_KVE + (long)ei * (2 * DO_));
        const float4* kt = (const float4*)(g_KVT + (long)ti * (2 * DO_));

        float t0 = 0.f, t1 = 0.f;
        float4 vb = make_float4(0.f, 0.f, 0.f, 0.f);
        if (act) {
            float4 b1 = kn[lane], c1 = ke[lane], d1 = kt[lane];
            float kx = b1.x + c1.x + d1.x;
            float ky = b1.y + c1.y + d1.y;
            float kz = b1.z + c1.z + d1.z;
            float kw_ = b1.w + c1.w + d1.w;
            float4 b2 = kn[25 + lane], c2 = ke[25 + lane], d2 = kt[25 + lane];
            vb.x = b2.x + c2.x + d2.x;
            vb.y = b2.y + c2.y + d2.y;
            vb.z = b2.z + c2.z + d2.z;
            vb.w = b2.w + c2.w + d2.w;
            float p0 = q.x * kx, p1 = q.y * ky, p2 = q.z * kz, p3 = q.w * kw_;
            t0 = (h0 ? p0 : 0.f) + (h1 ? p1 : 0.f) + (h2 ? p2 : 0.f) + (h3 ? p3 : 0.f);
            t1 = (h0 ? 0.f : p0) + (h1 ? 0.f : p1) + (h2 ? 0.f : p2) + (h3 ? 0.f : p3);
        }
#pragma unroll
        for (int off = 16; off; off >>= 1) {
            t0 += __shfl_xor_sync(0xffffffffu, t0, off);
            t1 += __shfl_xor_sync(0xffffffffu, t1, off);
        }
        float a0 = t0 > 0.f ? t0 : NEG_SLOPE * t0;
        float a1 = t1 > 0.f ? t1 : NEG_SLOPE * t1;
        // online softmax update, per head
        float nm0 = fmaxf(m0, a0);
        float c0 = __expf(m0 - nm0);
        float w0 = __expf(a0 - nm0);
        s0 = s0 * c0 + w0;
        m0 = nm0;
        float nm1 = fmaxf(m1, a1);
        float c1_ = __expf(m1 - nm1);
        float w1 = __expf(a1 - nm1);
        s1 = s1 * c1_ + w1;
        m1 = nm1;
        acc.x = acc.x * (h0 ? c0 : c1_) + (h0 ? w0 : w1) * vb.x;
        acc.y = acc.y * (h1 ? c0 : c1_) + (h1 ? w0 : w1) * vb.y;
        acc.z = acc.z * (h2 ? c0 : c1_) + (h2 ? w0 : w1) * vb.z;
        acc.w = acc.w * (h3 ? c0 : c1_) + (h3 ? w0 : w1) * vb.w;
    }

    if (act) {
        float r0 = s0 > 0.f ? 1.f / s0 : 0.f;
        float r1 = s1 > 0.f ? 1.f / s1 : 0.f;
        float4 o;
        o.x = acc.x * (h0 ? r0 : r1);
        o.y = acc.y * (h1 ? r0 : r1);
        o.z = acc.z * (h2 ? r0 : r1);
        o.w = acc.w * (h3 ? r0 : r1);
        ((float4*)(g_acc + (long)w * DO_))[lane] = o;
    }
}

// ---------------- finalize: out-proj + relu + layernorm ----------------
// dynamic smem: Wt[100][273] (transposed Wout, padded) + xs[4][272] + outs[4][100]
#define FIN_SMEM_FLOATS (DO_ * 273 + 4 * 272 + 4 * DO_)
__global__ __launch_bounds__(128)
void finalize_kernel(const float* __restrict__ nodeData,
                     const int* __restrict__ rev_nids,
                     const float* __restrict__ Wout,
                     const float* __restrict__ bout,
                     const float* __restrict__ ln_g,
                     const float* __restrict__ ln_b,
                     float* __restrict__ out) {
    extern __shared__ float sm[];
    float* Wt   = sm;                   // 100*273
    float* xs   = Wt + DO_ * 273;       // 4*272
    float* outs = xs + 4 * 272;         // 4*100
    int tid = threadIdx.x;

    for (int i = tid; i < 272 * DO_; i += blockDim.x) {
        int k = i / DO_, j = i - k * DO_;
        Wt[j * 273 + k] = Wout[i];
    }
    __syncthreads();

    for (int r0 = blockIdx.x * 4; r0 < NDST; r0 += gridDim.x * 4) {
        for (int i = tid; i < 4 * 272; i += blockDim.x) {
            int r = i / 272, k = i - r * 272;
            int row = r0 + r;
            float v = 0.f;
            if (row < NDST) {
                if (k < DO_) v = g_acc[(long)row * DO_ + k];
                else         v = nodeData[(long)rev_nids[row] * DN_ + (k - DO_)];
            }
            xs[r * 272 + k] = v;
        }
        __syncthreads();

        if (tid < DO_) {
            const float* wrow = Wt + tid * 273;
            float a0 = 0.f, a1 = 0.f, a2 = 0.f, a3 = 0.f;
#pragma unroll 4
            for (int k = 0; k < 272; k += 4) {
                float w0 = wrow[k], w1 = wrow[k + 1], w2 = wrow[k + 2], w3 = wrow[k + 3];
                float4 x0 = *(const float4*)(xs + 0 * 272 + k);
                float4 x1 = *(const float4*)(xs + 1 * 272 + k);
                float4 x2 = *(const float4*)(xs + 2 * 272 + k);
                float4 x3 = *(const float4*)(xs + 3 * 272 + k);
                a0 += w0 * x0.x + w1 * x0.y + w2 * x0.z + w3 * x0.w;
                a1 += w0 * x1.x + w1 * x1.y + w2 * x1.z + w3 * x1.w;
                a2 += w0 * x2.x + w1 * x2.y + w2 * x2.z + w3 * x2.w;
                a3 += w0 * x3.x + w1 * x3.y + w2 * x3.z + w3 * x3.w;
            }
            float bj = bout[tid];
            float v0 = a0 + bj, v1 = a1 + bj, v2 = a2 + bj, v3 = a3 + bj;
            outs[0 * DO_ + tid] = v0 > 0.f ? v0 : 0.f;
            outs[1 * DO_ + tid] = v1 > 0.f ? v1 : 0.f;
            outs[2 * DO_ + tid] = v2 > 0.f ? v2 : 0.f;
            outs[3 * DO_ + tid] = v3 > 0.f ? v3 : 0.f;
        }
        __syncthreads();

        int wr = tid >> 5, lane = tid & 31;
        int row = r0 + wr;
        if (row < NDST) {
            float s = 0.f, sq = 0.f;
            for (int j = lane; j < DO_; j += 32) {
                float v = outs[wr * DO_ + j];
                s += v; sq += v * v;
            }
#pragma unroll
            for (int off = 16; off; off >>= 1) {
                s  += __shfl_xor_sync(0xffffffffu, s, off);
                sq += __shfl_xor_sync(0xffffffffu, sq, off);
            }
            float mu  = s / (float)DO_;
            float var = sq / (float)DO_ - mu * mu;
            float inv = rsqrtf(var + 1e-5f);
            for (int j = lane; j < DO_; j += 32) {
                float v = (outs[wr * DO_ + j] - mu) * inv * ln_g[j] + ln_b[j];
                out[(long)row * DO_ + j] = v;
            }
        }
        __syncthreads();
    }
}

// ---------------- launch ----------------
extern "C" void kernel_launch(void* const* d_in, const int* in_sizes, int n_in,
                              void* d_out, int out_size) {
    const float* nodeData = (const float*)d_in[0];
    const float* efeat    = (const float*)d_in[1];
    const float* utd      = (const float*)d_in[2];
    const int*   rev_nids = (const int*)d_in[3];
    const int*   rev_eids = (const int*)d_in[4];
    const int*   rev_tids = (const int*)d_in[5];
    const int*   dstindex = (const int*)d_in[6];
    // d_in[7] = num_dst scalar (compile-time constant NDST)
    const float* time_w   = (const float*)d_in[8];
    const float* time_b   = (const float*)d_in[9];
    const float* Wqn      = (const float*)d_in[10];
    const float* bqn      = (const float*)d_in[11];
    const float* Wqt      = (const float*)d_in[12];
    const float* bqt      = (const float*)d_in[13];
    const float* Wkvn     = (const float*)d_in[14];
    const float* bkvn     = (const float*)d_in[15];
    const float* Wkve     = (const float*)d_in[16];
    const float* bkve     = (const float*)d_in[17];
    const float* Wkvt     = (const float*)d_in[18];
    const float* bkvt     = (const float*)d_in[19];
    const float* Wout     = (const float*)d_in[20];
    const float* bout     = (const float*)d_in[21];
    const float* ln_g     = (const float*)d_in[22];
    const float* ln_b     = (const float*)d_in[23];
    float* out = (float*)d_out;

    float *pTF, *pQ, *pKVN, *pKVE, *pKVT, *pbiasq;
    cudaGetSymbolAddress((void**)&pTF,    g_TF);
    cudaGetSymbolAddress((void**)&pQ,     g_Q);
    cudaGetSymbolAddress((void**)&pKVN,   g_KVN);
    cudaGetSymbolAddress((void**)&pKVE,   g_KVE);
    cudaGetSymbolAddress((void**)&pKVT,   g_KVT);
    cudaGetSymbolAddress((void**)&pbiasq, g_biasq);

    const int* node_inv = rev_nids + NDST;  // reverse_nids[num_dst:]

    // CSR build (independent of GEMMs)
    init_kernel<<<512, 256>>>();
    hist_kernel<<<2048, 256>>>(dstindex);
    scan_kernel<<<1, 1024>>>();
    scatter_kernel<<<2048, 256>>>(dstindex);

    biasq_kernel<<<1, 128>>>(time_b, Wqt, bqt, bqn);
    timefeat_kernel<<<8192, 256>>>(utd, time_w, time_b);

    // q[NDST,100] = nodeData[rev_nids[:NDST]] @ Wqn + (bqn + bqt + cos(tb)@Wqt)
    gemm128<true><<<dim3(2, (NDST + 127) / 128), 256>>>(
        nodeData, Wqn, pbiasq, pQ, rev_nids, NDST, DN_, DO_);
    // kvn[UN,200]
    gemm128<false><<<dim3(4, (UN + 127) / 128), 256>>>(
        nodeData, Wkvn, bkvn, pKVN, nullptr, UN, DN_, 2 * DO_);
    // kve[UE,200]
    gemm128<false><<<dim3(4, (UE + 127) / 128), 256>>>(
        efeat, Wkve, bkve, pKVE, nullptr, UE, DN_, 2 * DO_);
    // kvt[UT,200]
    gemm128<false><<<dim3(4, (UT + 127) / 128), 256>>>(
        pTF, Wkvt, bkvt, pKVT, nullptr, UT, DT_, 2 * DO_);

    // attention: one warp per dst, online softmax, no atomics
    attn_kernel<<<(NDST + 7) / 8, 256>>>(node_inv, rev_eids, rev_tids);

    // finalize
    cudaFuncSetAttribute(finalize_kernel,
                         cudaFuncAttributeMaxDynamicSharedMemorySize,
                         FIN_SMEM_FLOATS * (int)sizeof(float));
    finalize_kernel<<<296, 128, FIN_SMEM_FLOATS * (int)sizeof(float)>>>(
        nodeData, rev_nids, Wout, bout, ln_g, ln_b, out);
}